// round 16
// baseline (speedup 1.0000x reference)
#include <cuda_runtime.h>
#include <cuda_fp16.h>
#include <cstdint>

#define N_MAX   100000
#define E_MAX   3200000
#define C_DIM   40
#define F_DIM   128
#define CAP     128                  // bucket capacity per node (max deg ~70)
#define ROW_U4  8                    // 128B feature-row stride = 8 uint4

// ---------------- scratch (device globals; no allocation) ----------------
// NOTE: g_cur relies on (a) zero static initialization, (b) k_gather2_lsm
// resetting it to zero after final use -> every kernel_launch sees zeros.
__device__ int   g_is64;
__device__ int   g_vec;
__device__ int   g_cur[N_MAX];
__device__ int   g_bkt[(size_t)N_MAX * CAP];          // 51.2 MB bucket CSR
__device__ float g_dinv[N_MAX];
__device__ __align__(16) __half g_hA[(size_t)N_MAX * 64];   // 12.8 MB, 128B rows
__device__ __align__(16) __half g_hB[(size_t)N_MAX * 64];   // 12.8 MB

// ---------------- helpers ----------------
union H2U { __half2 h; unsigned u; };
__device__ __forceinline__ unsigned pack2(float a, float b) {
    H2U x; x.h = __floats2half2_rn(a, b); return x.u;
}
__device__ __forceinline__ float2 unpack2(unsigned u) {
    H2U x; x.u = u; return __half22float2(x.h);
}
__device__ __forceinline__ unsigned long long pack2f(float a, float b) {
    unsigned long long r;
    asm("mov.b64 %0, {%1,%2};" : "=l"(r) : "f"(a), "f"(b));
    return r;
}
__device__ __forceinline__ float2 unpack2f(unsigned long long v) {
    float a, b;
    asm("mov.b64 {%0,%1}, %2;" : "=f"(a), "=f"(b) : "l"(v));
    return make_float2(a, b);
}
__device__ __forceinline__ unsigned long long fma2(unsigned long long a,
                                                   unsigned long long b,
                                                   unsigned long long c) {
    unsigned long long d;
    asm("fma.rn.f32x2 %0, %1, %2, %3;" : "=l"(d) : "l"(a), "l"(b), "l"(c));
    return d;
}
// L2-cached (L1-bypass) vector load for streaming scattered rows.
__device__ __forceinline__ uint4 ldg_cg(const uint4* p) {
    uint4 v;
    asm volatile("ld.global.cg.v4.u32 {%0,%1,%2,%3}, [%4];"
                 : "=r"(v.x), "=r"(v.y), "=r"(v.z), "=r"(v.w) : "l"(p));
    return v;
}
// packed fp16 accumulate: h[j] += v[j] (4x HADD2)
__device__ __forceinline__ void hacc4(unsigned* h, uint4 v) {
    H2U x, y;
    x.u = h[0]; y.u = v.x; x.h = __hadd2(x.h, y.h); h[0] = x.u;
    x.u = h[1]; y.u = v.y; x.h = __hadd2(x.h, y.h); h[1] = x.u;
    x.u = h[2]; y.u = v.z; x.h = __hadd2(x.h, y.h); h[2] = x.u;
    x.u = h[3]; y.u = v.w; x.h = __hadd2(x.h, y.h); h[3] = x.u;
}

// Core gather: a[8] += sum of neighbor 16B chunks, fp16 chains flushed to f32
// every 16 edges (2 independent chains for MLP).
__device__ __forceinline__ void gather_rows(const uint4* __restrict__ src,
                                            const int* __restrict__ adj,
                                            int d, int part, float* a) {
    int k = 0;
    while (k < d) {
        int lim = (d - k < 16) ? (d - k) : 16;
        unsigned ha[4] = {0, 0, 0, 0}, hb[4] = {0, 0, 0, 0};
        int kk = 0;
#pragma unroll 1
        for (; kk + 2 <= lim; kk += 2) {
            int r0 = adj[k + kk];
            int r1 = adj[k + kk + 1];
            uint4 v0 = ldg_cg(src + (size_t)r0 * ROW_U4 + part);
            uint4 v1 = ldg_cg(src + (size_t)r1 * ROW_U4 + part);
            hacc4(ha, v0);
            hacc4(hb, v1);
        }
        if (kk < lim) {
            int r0 = adj[k + kk];
            hacc4(ha, ldg_cg(src + (size_t)r0 * ROW_U4 + part));
        }
#pragma unroll
        for (int j = 0; j < 4; ++j) {
            float2 fa = unpack2(ha[j]);
            float2 fb = unpack2(hb[j]);
            a[2 * j]     += fa.x + fb.x;
            a[2 * j + 1] += fa.y + fb.y;
        }
        k += lim;
    }
}

// ---------------- kernels ----------------

// detect edge dtype / vectorizability (1 warp).
__global__ void k_detect(const int* __restrict__ ei32, int E) {
    if (threadIdx.x == 0) {
        g_vec = ((E & 3) == 0) ? 1 : 0;
        int n = E < 64 ? E : 64;
        int is64 = 1;
        for (int j = 0; j < n; ++j)
            if (ei32[2 * j + 1] != 0) { is64 = 0; break; }
        g_is64 = is64;
    }
}

// Fused: first nGemm blocks do the raw projection GEMM (no dinv yet);
// remaining blocks do the bucket-CSR fill. Disjoint resources -> overlap.
__global__ void k_fillgemm(const float* __restrict__ X, const float* __restrict__ W,
                           const int* __restrict__ ei32, int E, int N, int nGemm) {
    __shared__ float2 ws2[20 * F_DIM];   // 20KB (only gemm blocks touch it)

    if ((int)blockIdx.x < nGemm) {
        for (int i = threadIdx.x; i < 20 * F_DIM; i += blockDim.x) {
            int cp = i >> 7;
            int k = i & 127;
            ws2[i] = make_float2(W[(size_t)(2 * cp) * F_DIM + k],
                                 W[(size_t)(2 * cp + 1) * F_DIM + k]);
        }
        __syncthreads();

        int n = blockIdx.x * blockDim.x + threadIdx.x;
        if (n >= N) return;

        const float4* xp = (const float4*)(X + (size_t)n * F_DIM);
        unsigned long long acc[20];
#pragma unroll
        for (int cp = 0; cp < 20; ++cp) acc[cp] = pack2f(0.0f, 0.0f);

#pragma unroll 1
        for (int ch = 0; ch < 8; ++ch) {
            float4 xv[4];
#pragma unroll
            for (int j = 0; j < 4; ++j) xv[j] = xp[ch * 4 + j];
            unsigned long long xq[16];
#pragma unroll
            for (int j = 0; j < 4; ++j) {
                xq[4 * j + 0] = pack2f(xv[j].x, xv[j].x);
                xq[4 * j + 1] = pack2f(xv[j].y, xv[j].y);
                xq[4 * j + 2] = pack2f(xv[j].z, xv[j].z);
                xq[4 * j + 3] = pack2f(xv[j].w, xv[j].w);
            }
#pragma unroll
            for (int cp = 0; cp < 20; ++cp) {
                const ulonglong2* wp = (const ulonglong2*)(ws2 + cp * F_DIM + ch * 16);
                unsigned long long a = acc[cp];
#pragma unroll
                for (int j = 0; j < 8; ++j) {
                    ulonglong2 w = wp[j];
                    a = fma2(xq[2 * j], w.x, a);
                    a = fma2(xq[2 * j + 1], w.y, a);
                }
                acc[cp] = a;
            }
        }

        uint4* yp = (uint4*)g_hA + (size_t)n * ROW_U4;
#pragma unroll
        for (int k = 0; k < 5; ++k) {
            float2 p0 = unpack2f(acc[4 * k + 0]);
            float2 p1 = unpack2f(acc[4 * k + 1]);
            float2 p2 = unpack2f(acc[4 * k + 2]);
            float2 p3 = unpack2f(acc[4 * k + 3]);
            uint4 u;
            u.x = pack2(p0.x, p0.y);
            u.y = pack2(p1.x, p1.y);
            u.z = pack2(p2.x, p2.y);
            u.w = pack2(p3.x, p3.y);
            yp[k] = u;
        }
    } else {
        // ---- fill branch: 4 edges per thread ----
        int t = ((int)blockIdx.x - nGemm) * blockDim.x + threadIdx.x;
        int e0 = t * 4;
        if (e0 >= E) return;
        int r[4], c[4];
        if (g_vec) {
            if (g_is64) {
                const int4* pr = (const int4*)ei32;
                int4 a = pr[e0 / 2], b = pr[e0 / 2 + 1];
                r[0] = a.x; r[1] = a.z; r[2] = b.x; r[3] = b.z;
                const int4* pc = (const int4*)(ei32 + 2 * (size_t)E);
                int4 u = pc[e0 / 2], v = pc[e0 / 2 + 1];
                c[0] = u.x; c[1] = u.z; c[2] = v.x; c[3] = v.z;
            } else {
                const int4* pr = (const int4*)ei32;
                int4 a = pr[e0 / 4];
                r[0] = a.x; r[1] = a.y; r[2] = a.z; r[3] = a.w;
                const int4* pc = (const int4*)(ei32 + (size_t)E);
                int4 u = pc[e0 / 4];
                c[0] = u.x; c[1] = u.y; c[2] = u.z; c[3] = u.w;
            }
            int p[4];
#pragma unroll
            for (int i = 0; i < 4; ++i)
                p[i] = atomicAdd(&g_cur[c[i]], 1);
#pragma unroll
            for (int i = 0; i < 4; ++i)
                if (p[i] < CAP) g_bkt[(size_t)c[i] * CAP + p[i]] = r[i];
        } else {
            for (int i = 0; i < 4 && e0 + i < E; ++i) {
                int e = e0 + i;
                int rr, cc;
                if (g_is64) { rr = ei32[2 * (size_t)e]; cc = ei32[2 * ((size_t)E + e)]; }
                else        { rr = ei32[e];             cc = ei32[(size_t)E + e]; }
                int pp = atomicAdd(&g_cur[cc], 1);
                if (pp < CAP) g_bkt[(size_t)cc * CAP + pp] = rr;
            }
        }
    }
}

// dinv[n] = rsqrt(deg+1); hA[n,:] *= dinv[n]  (in place). 5 thr/node.
__global__ void k_finish(int N) {
    int t = blockIdx.x * blockDim.x + threadIdx.x;
    int n = t / 5;
    int part = t % 5;
    if (n >= N) return;
    int d = g_cur[n];
    float dn = rsqrtf((float)(d + 1));
    if (part == 0) g_dinv[n] = dn;
    uint4* p = (uint4*)g_hA + (size_t)n * ROW_U4 + part;
    uint4 v = *p;
    float2 f0 = unpack2(v.x), f1 = unpack2(v.y), f2 = unpack2(v.z), f3 = unpack2(v.w);
    uint4 u;
    u.x = pack2(dn * f0.x, dn * f0.y);
    u.y = pack2(dn * f1.x, dn * f1.y);
    u.z = pack2(dn * f2.x, dn * f2.y);
    u.w = pack2(dn * f3.x, dn * f3.y);
    *p = u;
}

// hop 1: hB[n] = fp16( dinv[n]^2 * (hA[n] + sum hA[r]) ).  5 thr/node, 16B each.
__global__ void __launch_bounds__(320, 5) k_gather1(int N) {
    int t = blockIdx.x * blockDim.x + threadIdx.x;
    int n = t / 5;
    int part = t % 5;
    if (n >= N) return;

    int d = g_cur[n];
    d = d < CAP ? d : CAP;
    const int* adj = g_bkt + (size_t)n * CAP;
    const uint4* src = (const uint4*)g_hA;

    float a[8];
    {
        uint4 v = src[(size_t)n * ROW_U4 + part];
        float2 f0 = unpack2(v.x), f1 = unpack2(v.y), f2 = unpack2(v.z), f3 = unpack2(v.w);
        a[0] = f0.x; a[1] = f0.y; a[2] = f1.x; a[3] = f1.y;
        a[4] = f2.x; a[5] = f2.y; a[6] = f3.x; a[7] = f3.y;
    }

    gather_rows(src, adj, d, part, a);

    float dn = g_dinv[n];
    float sc = dn * dn;
    uint4 u;
    u.x = pack2(sc * a[0], sc * a[1]);
    u.y = pack2(sc * a[2], sc * a[3]);
    u.z = pack2(sc * a[4], sc * a[5]);
    u.w = pack2(sc * a[6], sc * a[7]);
    ((uint4*)g_hB)[(size_t)n * ROW_U4 + part] = u;
}

// hop 2 fused with bias + log_softmax. 6 nodes/warp, 5 lanes/node.
// Also resets g_cur[n] = 0 after last use (zero invariant for next launch).
__global__ void __launch_bounds__(256, 6) k_gather2_lsm(const float* __restrict__ bias,
                                                        float* __restrict__ out, int N) {
    int lane = threadIdx.x & 31;
    int warp = (blockIdx.x * blockDim.x + threadIdx.x) >> 5;
    int li = lane / 5;
    int part = lane - li * 5;
    int n = warp * 6 + li;
    bool active = (li < 6) && (n < N);

    float a[8] = {0, 0, 0, 0, 0, 0, 0, 0};

    if (active) {
        int d = g_cur[n];
        if (part == 0) g_cur[n] = 0;       // restore zero invariant
        d = d < CAP ? d : CAP;
        const int* adj = g_bkt + (size_t)n * CAP;
        const uint4* src = (const uint4*)g_hB;
        {
            uint4 v = src[(size_t)n * ROW_U4 + part];
            float2 f0 = unpack2(v.x), f1 = unpack2(v.y), f2 = unpack2(v.z), f3 = unpack2(v.w);
            a[0] = f0.x; a[1] = f0.y; a[2] = f1.x; a[3] = f1.y;
            a[4] = f2.x; a[5] = f2.y; a[6] = f3.x; a[7] = f3.y;
        }
        gather_rows(src, adj, d, part, a);

        float dn = g_dinv[n];
#pragma unroll
        for (int i = 0; i < 8; ++i) a[i] = dn * a[i] + bias[part * 8 + i];
    }

    int gbase = li * 5;
    float m = a[0];
#pragma unroll
    for (int i = 1; i < 8; ++i) m = fmaxf(m, a[i]);
    if (!active) m = -3.0e38f;
#pragma unroll
    for (int k = 1; k <= 4; k <<= 1) {
        int srcl = gbase + (part + k) % 5;
        float o = __shfl_sync(0xffffffffu, m, srcl, 32);
        m = fmaxf(m, o);
    }
    float s = 0.0f;
    if (active) {
#pragma unroll
        for (int i = 0; i < 8; ++i) s += __expf(a[i] - m);
    }
    float s_orig = s;
    {
        int srcl = gbase + (part + 1) % 5;
        s += __shfl_sync(0xffffffffu, s, srcl, 32);        // span 2
        srcl = gbase + (part + 2) % 5;
        s += __shfl_sync(0xffffffffu, s, srcl, 32);        // span 4
        srcl = gbase + (part + 4) % 5;
        s += __shfl_sync(0xffffffffu, s_orig, srcl, 32);   // + the 5th
    }

    if (!active) return;
    float l = m + __logf(s);

    float4* op = (float4*)(out + (size_t)n * C_DIM + part * 8);
    op[0] = make_float4(a[0] - l, a[1] - l, a[2] - l, a[3] - l);
    op[1] = make_float4(a[4] - l, a[5] - l, a[6] - l, a[7] - l);
}

// ---------------- launch ----------------
extern "C" void kernel_launch(void* const* d_in, const int* in_sizes, int n_in,
                              void* d_out, int out_size) {
    const float* X    = (const float*)d_in[0];      // [N, 128]
    const float* W    = (const float*)d_in[1];      // [40, 128]
    const float* bias = (const float*)d_in[2];      // [40]
    const int*   ei   = (const int*)d_in[3];        // [2, E] int32 or int64
    (void)n_in;

    const int N = in_sizes[0] / F_DIM;
    const int E = in_sizes[3] / 2;
    float* out = (float*)d_out;
    (void)out_size;

    const int TB = 256;
    const int nGemm = (N + TB - 1) / TB;
    const int nFill = (E / 4 + TB) / TB;

    k_detect<<<1, 32>>>(ei, E);                                 // 1

    k_fillgemm<<<nGemm + nFill, TB>>>(X, W, ei, E, N, nGemm);   // 2: fill || gemm

    dim3 gF((N * 5 + TB - 1) / TB);
    k_finish<<<gF, TB>>>(N);                                    // 3

    const int GB = 320;
    dim3 gG(((size_t)N * 5 + GB - 1) / GB);
    k_gather1<<<gG, GB>>>(N);                                   // 4

    dim3 gL((N + 47) / 48);
    k_gather2_lsm<<<gL, TB>>>(bias, out, N);                    // 5
}